// round 3
// baseline (speedup 1.0000x reference)
#include <cuda_runtime.h>
#include <cstdint>

// CARAFE: N=4, C=256, H=W=64, K=5, G=1, S=2  ->  out [4,256,128,128] f32
#define KK   5
#define N_   4
#define C_   256
#define H_   64
#define W_   64
#define HO   128
#define WO   128

#define TH_CELLS 4          // input cells per CTA (rows)
#define TW_CELLS 8          // input cells per CTA (cols)
#define PR 8                // patch rows = TH_CELLS + 4
#define PC 12               // patch cols = TW_CELLS + 4
#define PSTR 12             // smem row stride (floats): (hh*12+ww)%32 is a perfect warp permutation
#define PLANE (PR * PSTR)   // 96 floats per channel plane
#define NCH_STAGE 8
#define NSTAGE 32
#define NTHREADS 128
#define NLOAD (NCH_STAGE * PLANE)   // 768
#define LPT (NLOAD / NTHREADS)      // 6

typedef unsigned long long ull;

__device__ __forceinline__ ull pack2(float lo, float hi) {
    ull r;
    asm("mov.b64 %0, {%1, %2};" : "=l"(r) : "f"(lo), "f"(hi));
    return r;
}
__device__ __forceinline__ void ffma2(ull& d, ull a, ull b) {
    asm("fma.rn.f32x2 %0, %1, %2, %0;" : "+l"(d) : "l"(a), "l"(b));
}

__global__ void __launch_bounds__(NTHREADS, 3)
carafe_kernel(const float* __restrict__ feat, const float* __restrict__ masks,
              float* __restrict__ out)
{
    __shared__ __align__(16) float sbuf[2][NCH_STAGE * PLANE];  // 2*768*4 = 6144 B

    const int t    = threadIdx.x;
    const int slot = t >> 5;          // 0..3 : channel slot (uniform per warp)
    const int cid  = t & 31;          // cell within 4x8 tile
    const int hh   = cid >> 3;        // 0..3
    const int ww   = cid & 7;         // 0..7

    const int b   = blockIdx.x;       // 0..511
    const int n   = b >> 7;
    const int tid = b & 127;
    const int th  = tid >> 3;         // 0..15
    const int tw  = tid & 7;          // 0..7
    const int h0  = th * TH_CELLS;
    const int w0  = tw * TW_CELLS;
    const int oh  = (h0 + hh) * 2;
    const int ow  = (w0 + ww) * 2;

    // ---- per-thread masks: 25 taps x 2 output rows, f32x2-packed over q ----
    ull m0[25], m1[25];
    {
        const float* mb = masks + (size_t)n * 25 * (HO * WO) + (size_t)oh * WO + ow;
        #pragma unroll
        for (int k = 0; k < 25; ++k) {
            const float2 a = __ldg((const float2*)(mb + (size_t)k * (HO * WO)));
            const float2 c = __ldg((const float2*)(mb + (size_t)k * (HO * WO) + WO));
            m0[k] = pack2(a.x, a.y);
            m1[k] = pack2(c.x, c.y);
        }
    }

    // ---- cooperative-load slots ----
    const float* fbase = feat + (size_t)n * (C_ * H_ * W_);
    int sofs[LPT], gofs[LPT];
    #pragma unroll
    for (int i = 0; i < LPT; ++i) {
        const int e   = t + i * NTHREADS;     // < 768
        const int ch  = e / PLANE;
        const int rem = e - ch * PLANE;
        const int r   = rem / PSTR;
        const int col = rem - r * PSTR;
        const int gr  = h0 - 2 + r;
        const int gc  = w0 - 2 + col;
        sofs[i] = e;
        gofs[i] = ((unsigned)gr < (unsigned)H_ && (unsigned)gc < (unsigned)W_)
                      ? (ch * (H_ * W_) + gr * W_ + gc)
                      : -1;
    }

    float v[LPT];

    // prologue: stage 0 -> buffer 0
    #pragma unroll
    for (int i = 0; i < LPT; ++i)
        v[i] = (gofs[i] >= 0) ? __ldg(fbase + gofs[i]) : 0.f;
    #pragma unroll
    for (int i = 0; i < LPT; ++i)
        sbuf[0][sofs[i]] = v[i];
    __syncthreads();

    float* obase = out + (size_t)n * (C_ * HO * WO) + (size_t)oh * WO + ow;

    for (int s = 0; s < NSTAGE; ++s) {
        // prefetch next stage's features
        if (s + 1 < NSTAGE) {
            const float* fb = fbase + (size_t)(s + 1) * NCH_STAGE * (H_ * W_);
            #pragma unroll
            for (int i = 0; i < LPT; ++i)
                v[i] = (gofs[i] >= 0) ? __ldg(fb + gofs[i]) : 0.f;
        }

        // compute: 2 channels x (2 rows x 2 cols packed-q), 25 taps
        const float* fA = &sbuf[s & 1][0] + (2 * slot) * PLANE + hh * PSTR + ww;
        const float* fB = fA + PLANE;
        ull aA0 = 0, aA1 = 0, aB0 = 0, aB1 = 0;
        #pragma unroll
        for (int ki = 0; ki < KK; ++ki) {
            #pragma unroll
            for (int kj = 0; kj < KK; ++kj) {
                const int k   = ki * KK + kj;
                const int off = ki * PSTR + kj;
                const float a = fA[off];
                const float c = fB[off];
                const ull pa = pack2(a, a);
                const ull pc = pack2(c, c);
                ffma2(aA0, pa, m0[k]);
                ffma2(aA1, pa, m1[k]);
                ffma2(aB0, pc, m0[k]);
                ffma2(aB1, pc, m1[k]);
            }
        }

        // stores: 2 channels x 2 rows, 8-byte coalesced
        {
            const int cA = s * NCH_STAGE + 2 * slot;
            ull* oA = (ull*)(obase + (size_t)cA * (HO * WO));
            ull* oB = (ull*)(obase + (size_t)(cA + 1) * (HO * WO));
            oA[0]      = aA0;
            oA[WO / 2] = aA1;
            oB[0]      = aB0;
            oB[WO / 2] = aB1;
        }

        // commit prefetched data into the other buffer
        if (s + 1 < NSTAGE) {
            float* dst = &sbuf[(s + 1) & 1][0];
            #pragma unroll
            for (int i = 0; i < LPT; ++i)
                dst[sofs[i]] = v[i];
        }
        __syncthreads();
    }
}

extern "C" void kernel_launch(void* const* d_in, const int* in_sizes, int n_in,
                              void* d_out, int out_size) {
    const float* feat  = (const float*)d_in[0];
    const float* masks = (const float*)d_in[1];
    if (n_in >= 2 && in_sizes[0] == N_ * KK * KK * HO * WO &&
        in_sizes[1] == N_ * C_ * H_ * W_) {
        const float* tmp = feat; feat = masks; masks = tmp;
    }
    carafe_kernel<<<N_ * 128, NTHREADS>>>(feat, masks, (float*)d_out);
}